// round 7
// baseline (speedup 1.0000x reference)
#include <cuda_runtime.h>
#include <math.h>

#define BB 64
#define PP 8732
#define CC 81
#define TPB 256
#define PPB 64                        // priors per block
#define GRID_X ((PP + PPB - 1) / PPB) // 137
#define NBLOCKS (GRID_X * BB)         // 8768

// ---- device scratch (no allocations allowed) ----
__device__ double d_loss_l, d_loss_fc;
__device__ double d_ce_all[BB], d_ce_pos[BB];
__device__ int    d_numpos[BB];
__device__ double d_rowC[BB];
__device__ float  d_ce_row[PP];   // one-row buffer, fallback path only
__device__ int    d_done;

__global__ void k_init() {
    int i = threadIdx.x;
    if (i == 0) { d_loss_l = 0.0; d_loss_fc = 0.0; d_done = 0; }
    if (i < BB) { d_ce_all[i] = 0.0; d_ce_pos[i] = 0.0; d_numpos[i] = 0; d_rowC[i] = 0.0; }
}

__global__ __launch_bounds__(TPB) void k_fused(
    const float* __restrict__ loc_data, const float* __restrict__ conf,
    const float* __restrict__ fc_data,  const float* __restrict__ loc_t,
    const float* __restrict__ fc_t,     const int* __restrict__ conf_t,
    float* __restrict__ out)
{
    const int b    = blockIdx.y;
    const int tid  = threadIdx.x;
    const int lane = tid & 31;
    const int warp = tid >> 5;
    const int p0   = blockIdx.x * PPB;
    const int nloc = (PP - p0 < PPB) ? (PP - p0) : PPB;   // 64 or 28
    const unsigned rowp = (unsigned)(b * PP + p0);        // fits 32-bit

    __shared__ float  s_exp[PPB * CC];                    // exp(conf), 20736 B
    __shared__ float  s_part[TPB];
    __shared__ int    s_t[PPB];
    __shared__ float  rl[8], rf[8], rc[8], rp[8];
    __shared__ int    rn[8];
    __shared__ int    islast, nfb, fbrows[BB];
    __shared__ int    sh[TPB];
    __shared__ double shd[TPB];
    __shared__ double fin[2][2];

    // ---- front-batched loads: conf_t + loc/fc (unconditional, masked later) ----
    int   myt  = 0;
    float locs = 0.f, fcs = 0.f;
    if (tid < nloc) {
        myt = conf_t[rowp + tid];
        const unsigned pi = rowp + tid;
        float4 a0 = __ldcs((const float4*)loc_data + pi);
        float4 t0 = __ldcs((const float4*)loc_t    + pi);
        float4 b0 = __ldcs((const float4*)fc_data + pi * 2u);
        float4 u0 = __ldcs((const float4*)fc_t    + pi * 2u);
        float4 b1 = __ldcs((const float4*)fc_data + pi * 2u + 1);
        float4 u1 = __ldcs((const float4*)fc_t    + pi * 2u + 1);
        float d;
        d = fabsf(a0.x - t0.x); locs += (d < 1.f) ? 0.5f*d*d : d - 0.5f;
        d = fabsf(a0.y - t0.y); locs += (d < 1.f) ? 0.5f*d*d : d - 0.5f;
        d = fabsf(a0.z - t0.z); locs += (d < 1.f) ? 0.5f*d*d : d - 0.5f;
        d = fabsf(a0.w - t0.w); locs += (d < 1.f) ? 0.5f*d*d : d - 0.5f;
        d = fabsf(b0.x - u0.x); fcs  += (d < 1.f) ? 0.5f*d*d : d - 0.5f;
        d = fabsf(b0.y - u0.y); fcs  += (d < 1.f) ? 0.5f*d*d : d - 0.5f;
        d = fabsf(b0.z - u0.z); fcs  += (d < 1.f) ? 0.5f*d*d : d - 0.5f;
        d = fabsf(b0.w - u0.w); fcs  += (d < 1.f) ? 0.5f*d*d : d - 0.5f;
        d = fabsf(b1.x - u1.x); fcs  += (d < 1.f) ? 0.5f*d*d : d - 0.5f;
        d = fabsf(b1.y - u1.y); fcs  += (d < 1.f) ? 0.5f*d*d : d - 0.5f;
        d = fabsf(b1.z - u1.z); fcs  += (d < 1.f) ? 0.5f*d*d : d - 0.5f;
        d = fabsf(b1.w - u1.w); fcs  += (d < 1.f) ? 0.5f*d*d : d - 0.5f;
        s_t[tid] = myt;
        if (myt == 0) { locs = 0.f; fcs = 0.f; }
    }

    // ---- streaming stage: load float4, exponentiate inline, store exp to smem ----
    const int nvec = nloc * CC / 4;                       // 64*81/4=1296 or 567
    const float4* c4 = (const float4*)conf + (rowp * (unsigned)CC) / 4u;
    float4* s4 = (float4*)s_exp;
    #pragma unroll 3
    for (int i = tid; i < nvec; i += TPB) {
        float4 v = __ldcs(c4 + i);
        float4 e;
        e.x = __expf(v.x); e.y = __expf(v.y);
        e.z = __expf(v.z); e.w = __expf(v.w);
        s4[i] = e;
    }
    __syncthreads();

    // ---- 4-way split-row sum of exps (threads tid, tid+64, +128, +192 share prior) ----
    {
        const int prior = tid & 63;
        const int q     = tid >> 6;
        float part = 0.f;
        if (prior < nloc) {
            const float* row = s_exp + prior * CC + q * 20;
            float a0 = 0.f, a1 = 0.f, a2 = 0.f, a3 = 0.f;
            #pragma unroll
            for (int c = 0; c < 20; c += 4) {
                a0 += row[c]; a1 += row[c+1]; a2 += row[c+2]; a3 += row[c+3];
            }
            part = (a0 + a1) + (a2 + a3);
            if (q == 3) part += row[20];                  // element 80
        }
        s_part[tid] = part;
    }
    __syncthreads();

    // ---- per-prior ce ----
    float ces = 0.f, cep = 0.f;
    int   np = 0;
    if (tid < nloc) {
        float s = (s_part[tid] + s_part[tid + 64]) + (s_part[tid + 128] + s_part[tid + 192]);
        float g = s_exp[tid * CC + myt];
        float ce = __logf(s) - __logf(g);
        ces = ce;
        if (myt > 0) { cep = ce; np = 1; }
    }

    // ---- block reduce + atomics ----
    #pragma unroll
    for (int o = 16; o; o >>= 1) {
        locs += __shfl_xor_sync(0xffffffffu, locs, o);
        fcs  += __shfl_xor_sync(0xffffffffu, fcs,  o);
        ces  += __shfl_xor_sync(0xffffffffu, ces,  o);
        cep  += __shfl_xor_sync(0xffffffffu, cep,  o);
        np   += __shfl_xor_sync(0xffffffffu, np,   o);
    }
    if (lane == 0) { rl[warp]=locs; rf[warp]=fcs; rc[warp]=ces; rp[warp]=cep; rn[warp]=np; }
    __syncthreads();
    if (tid == 0) {
        float L=0.f,F=0.f,Ce=0.f,Cp=0.f; int Np=0;
        #pragma unroll
        for (int w = 0; w < 8; ++w) { L+=rl[w]; F+=rf[w]; Ce+=rc[w]; Cp+=rp[w]; Np+=rn[w]; }
        atomicAdd(&d_loss_l,  (double)L);
        atomicAdd(&d_loss_fc, (double)F);
        atomicAdd(&d_ce_all[b], (double)Ce);
        atomicAdd(&d_ce_pos[b], (double)Cp);
        atomicAdd(&d_numpos[b], Np);
    }

    // ---- completion handshake: last block does mining + finalize ----
    __threadfence();
    if (tid == 0) islast = (atomicAdd(&d_done, 1) == NBLOCKS - 1);
    __syncthreads();
    if (!islast) return;
    __threadfence();

    // per-row selection. fast path: num_neg >= #negatives -> row sum = all ce.
    if (tid == 0) nfb = 0;
    __syncthreads();
    if (tid < BB) {
        int npb = d_numpos[tid];
        long k3 = 3L * (long)npb;
        int k = (k3 < (long)(PP - 1)) ? (int)k3 : (PP - 1);
        int nneg = PP - npb;
        if (k >= nneg)      d_rowC[tid] = d_ce_all[tid];
        else if (k <= 0)    d_rowC[tid] = d_ce_pos[tid];
        else { int s = atomicAdd(&nfb, 1); fbrows[s] = tid; }
    }
    __syncthreads();

    // exact fallback (never triggered on this data): recompute ce for the row,
    // then bit-bisection for the k-th largest negative ce.
    for (int fi = 0; fi < nfb; ++fi) {
        int bb = fbrows[fi];
        long rb = (long)bb * PP;
        for (int i = warp; i < PP; i += 8) {
            const long cb = (rb + i) * CC;
            float v0 = conf[cb + lane];
            float v1 = conf[cb + lane + 32];
            float v2 = (lane < CC - 64) ? conf[cb + lane + 64] : 0.f;
            float s = __expf(v0) + __expf(v1);
            if (lane < CC - 64) s += __expf(v2);
            #pragma unroll
            for (int o = 16; o; o >>= 1) s += __shfl_xor_sync(0xffffffffu, s, o);
            int t = conf_t[rb + i];
            float cand = (t < 32) ? v0 : (t < 64) ? v1 : v2;
            float gath = __shfl_sync(0xffffffffu, cand, t & 31);
            if (lane == 0) d_ce_row[i] = __logf(s) - gath;
        }
        __syncthreads();
        int npb = d_numpos[bb];
        long k3 = 3L * (long)npb;
        int k = (k3 < (long)(PP - 1)) ? (int)k3 : (PP - 1);
        unsigned lo = 0u, hi = 0x7f800000u;
        while (lo < hi) {
            unsigned mid = lo + (hi - lo + 1u) / 2u;
            int c = 0;
            for (int i = tid; i < PP; i += TPB)
                if (conf_t[rb + i] == 0 &&
                    __float_as_uint(fmaxf(d_ce_row[i], 0.f)) >= mid) c++;
            sh[tid] = c; __syncthreads();
            for (int s = TPB/2; s; s >>= 1) { if (tid < s) sh[tid] += sh[tid + s]; __syncthreads(); }
            int tot = sh[0]; __syncthreads();
            if (tot >= k) lo = mid; else hi = mid - 1u;
        }
        int c = 0; double su = 0.0;
        for (int i = tid; i < PP; i += TPB) {
            if (conf_t[rb + i] == 0) {
                float v = d_ce_row[i];
                if (__float_as_uint(fmaxf(v, 0.f)) > lo) { c++; su += (double)v; }
            }
        }
        sh[tid] = c; shd[tid] = su; __syncthreads();
        for (int s = TPB/2; s; s >>= 1) {
            if (tid < s) { sh[tid] += sh[tid + s]; shd[tid] += shd[tid + s]; }
            __syncthreads();
        }
        if (tid == 0)
            d_rowC[bb] = d_ce_pos[bb] + shd[0] + (double)(k - sh[0]) * (double)__uint_as_float(lo);
        __syncthreads();
    }

    // ---- finalize (parallel) ----
    double n = (tid < BB) ? (double)d_numpos[tid] : 0.0;
    double c = (tid < BB) ? d_rowC[tid] : 0.0;
    if (tid < 64) {
        #pragma unroll
        for (int o = 16; o; o >>= 1) {
            n += __shfl_xor_sync(0xffffffffu, n, o);
            c += __shfl_xor_sync(0xffffffffu, c, o);
        }
        if (lane == 0) { fin[warp][0] = n; fin[warp][1] = c; }
    }
    __syncthreads();
    if (tid == 0) {
        double N  = fin[0][0] + fin[1][0];
        double Cc = fin[0][1] + fin[1][1];
        out[0] = (float)(d_loss_l / N);
        out[1] = (float)(Cc / N);
        out[2] = (float)(d_loss_fc / N);
    }
}

extern "C" void kernel_launch(void* const* d_in, const int* in_sizes, int n_in,
                              void* d_out, int out_size) {
    const float* loc_data = (const float*)d_in[0];
    const float* conf     = (const float*)d_in[1];
    const float* fc_data  = (const float*)d_in[2];
    const float* loc_t    = (const float*)d_in[3];
    const float* fc_t     = (const float*)d_in[4];
    const int*   conf_t   = (const int*)d_in[5];

    k_init<<<1, 64>>>();
    dim3 grid(GRID_X, BB);
    k_fused<<<grid, TPB>>>(loc_data, conf, fc_data, loc_t, fc_t, conf_t, (float*)d_out);
}

// round 8
// speedup vs baseline: 1.6281x; 1.6281x over previous
#include <cuda_runtime.h>
#include <cuda_pipeline.h>
#include <math.h>

#define BB 64
#define PP 8732
#define CC 81
#define TPB 256
#define PPB 128
#define GRID_X ((PP + PPB - 1) / PPB) // 69
#define NBLOCKS (GRID_X * BB)         // 4416
#define SPP 32                        // priors per pipeline stage
#define NSTG 4
#define VPS (SPP * CC / 4)            // 648 float4 per stage

// ---- dynamic smem layout (float offsets) ----
#define OFF_CONF 0                    // 128*81 raw conf            (41472 B)
#define OFF_LOC   10368               // 128 float4                 ( 2048 B)
#define OFF_LOCT  10880
#define OFF_FC    11392               // 256 float4                 ( 4096 B)
#define OFF_FCT   12416
#define OFF_T     13440               // 128 int
#define OFF_PS    13568               // 256 partials
#define OFF_SUM   13824               // 128 row sums
#define OFF_RL    13952
#define OFF_RF    13960
#define OFF_RC    13968
#define OFF_RP    13976
#define OFF_RN    13984               // 8 int
#define OFF_ISL   13992
#define OFF_NFB   13993
#define OFF_FBR   13994               // 64 int
#define OFF_FIN   14060               // 4 doubles (byte 56240, 8-aligned)
#define SMEM_FLOATS 14068
#define SMEM_BYTES (SMEM_FLOATS * 4)  // 56272

// ---- device scratch (no allocations allowed) ----
__device__ double d_loss_l, d_loss_fc;
__device__ double d_ce_all[BB], d_ce_pos[BB];
__device__ int    d_numpos[BB];
__device__ double d_rowC[BB];
__device__ float  d_ce_row[PP];   // one-row buffer, fallback path only
__device__ int    d_done;

__global__ void k_init() {
    int i = threadIdx.x;
    if (i == 0) { d_loss_l = 0.0; d_loss_fc = 0.0; d_done = 0; }
    if (i < BB) { d_ce_all[i] = 0.0; d_ce_pos[i] = 0.0; d_numpos[i] = 0; d_rowC[i] = 0.0; }
}

__global__ __launch_bounds__(TPB) void k_fused(
    const float* __restrict__ loc_data, const float* __restrict__ conf,
    const float* __restrict__ fc_data,  const float* __restrict__ loc_t,
    const float* __restrict__ fc_t,     const int* __restrict__ conf_t,
    float* __restrict__ out)
{
    extern __shared__ float sm[];
    float4* s_conf4 = (float4*)(sm + OFF_CONF);
    float*  s_conf  = sm + OFF_CONF;
    float4* s_loc4  = (float4*)(sm + OFF_LOC);
    float4* s_loct4 = (float4*)(sm + OFF_LOCT);
    float4* s_fc4   = (float4*)(sm + OFF_FC);
    float4* s_fct4  = (float4*)(sm + OFF_FCT);
    int*    s_t     = (int*)(sm + OFF_T);
    float*  s_ps    = sm + OFF_PS;
    float*  s_sum   = sm + OFF_SUM;
    int*    s_isl   = (int*)(sm + OFF_ISL);
    int*    s_nfb   = (int*)(sm + OFF_NFB);
    int*    s_fbr   = (int*)(sm + OFF_FBR);
    double* s_fin   = (double*)(sm + OFF_FIN);

    const int b    = blockIdx.y;
    const int tid  = threadIdx.x;
    const int lane = tid & 31;
    const int warp = tid >> 5;
    const int p0   = blockIdx.x * PPB;
    const int nloc = (PP - p0 < PPB) ? (PP - p0) : PPB;   // 128 or 28
    const unsigned rowp = (unsigned)(b * PP + p0);
    const int nvecT = nloc * CC / 4;

    const float4* csrc = (const float4*)conf + (rowp * (unsigned)CC) / 4u;

    // ---- issue ALL loads up front via cp.async (registerless MLP) ----
    // commit s covers conf stage s; last commit also carries targets + loc/fc.
    #pragma unroll
    for (int s = 0; s < NSTG; ++s) {
        int v0 = s * VPS;
        int v1 = (s + 1) * VPS; if (v1 > nvecT) v1 = nvecT;
        for (int i = v0 + tid; i < v1; i += TPB)
            __pipeline_memcpy_async(s_conf4 + i, csrc + i, 16);
        if (s == 0) {
            if (tid < nloc / 4)
                __pipeline_memcpy_async((float4*)s_t + tid,
                                        (const float4*)(conf_t + rowp) + tid, 16);
        }
        if (s == NSTG - 1) {
            if (tid < nloc) {
                __pipeline_memcpy_async(s_loc4  + tid, (const float4*)loc_data + rowp + tid, 16);
                __pipeline_memcpy_async(s_loct4 + tid, (const float4*)loc_t    + rowp + tid, 16);
            }
            for (int i = tid; i < 2 * nloc; i += TPB) {
                __pipeline_memcpy_async(s_fc4  + i, (const float4*)fc_data + rowp * 2u + i, 16);
                __pipeline_memcpy_async(s_fct4 + i, (const float4*)fc_t    + rowp * 2u + i, 16);
            }
        }
        __pipeline_commit();
    }

    // ---- staged compute: exp+partial-sum as each stage lands ----
    #pragma unroll
    for (int s = 0; s < NSTG; ++s) {
        __pipeline_wait_prior(NSTG - 1 - s);
        __syncthreads();
        const int pr  = s * SPP + (tid >> 3);
        const int seg = tid & 7;
        float part = 0.f;
        if (pr < nloc) {
            const float* row = s_conf + pr * CC + seg * 10;
            float a0 = 0.f, a1 = 0.f;
            #pragma unroll
            for (int c = 0; c < 10; c += 2) {
                a0 += __expf(row[c]);
                a1 += __expf(row[c + 1]);
            }
            if (seg == 7) a0 += __expf(row[10]);     // element 80
            part = a0 + a1;
        }
        s_ps[tid] = part;
        __syncthreads();
        if (tid < SPP) {
            const float* p8 = s_ps + tid * 8;
            s_sum[s * SPP + tid] =
                ((p8[0] + p8[1]) + (p8[2] + p8[3])) + ((p8[4] + p8[5]) + (p8[6] + p8[7]));
        }
    }
    __syncthreads();

    // ---- per-prior: exact ce = log(sum) - v_t ; loc/fc smooth-L1 from smem ----
    float locs = 0.f, fcs = 0.f, ces = 0.f, cep = 0.f;
    int   np = 0;
    if (tid < nloc) {
        int t = s_t[tid];
        float ce = __logf(s_sum[tid]) - s_conf[tid * CC + t];
        ces = ce;
        if (t > 0) {
            cep = ce; np = 1;
            float4 a0 = s_loc4[tid],      t0 = s_loct4[tid];
            float4 b0 = s_fc4[tid * 2],   u0 = s_fct4[tid * 2];
            float4 b1 = s_fc4[tid * 2+1], u1 = s_fct4[tid * 2+1];
            float d;
            d = fabsf(a0.x - t0.x); locs += (d < 1.f) ? 0.5f*d*d : d - 0.5f;
            d = fabsf(a0.y - t0.y); locs += (d < 1.f) ? 0.5f*d*d : d - 0.5f;
            d = fabsf(a0.z - t0.z); locs += (d < 1.f) ? 0.5f*d*d : d - 0.5f;
            d = fabsf(a0.w - t0.w); locs += (d < 1.f) ? 0.5f*d*d : d - 0.5f;
            d = fabsf(b0.x - u0.x); fcs  += (d < 1.f) ? 0.5f*d*d : d - 0.5f;
            d = fabsf(b0.y - u0.y); fcs  += (d < 1.f) ? 0.5f*d*d : d - 0.5f;
            d = fabsf(b0.z - u0.z); fcs  += (d < 1.f) ? 0.5f*d*d : d - 0.5f;
            d = fabsf(b0.w - u0.w); fcs  += (d < 1.f) ? 0.5f*d*d : d - 0.5f;
            d = fabsf(b1.x - u1.x); fcs  += (d < 1.f) ? 0.5f*d*d : d - 0.5f;
            d = fabsf(b1.y - u1.y); fcs  += (d < 1.f) ? 0.5f*d*d : d - 0.5f;
            d = fabsf(b1.z - u1.z); fcs  += (d < 1.f) ? 0.5f*d*d : d - 0.5f;
            d = fabsf(b1.w - u1.w); fcs  += (d < 1.f) ? 0.5f*d*d : d - 0.5f;
        }
    }

    // ---- block reduce + atomics ----
    #pragma unroll
    for (int o = 16; o; o >>= 1) {
        locs += __shfl_xor_sync(0xffffffffu, locs, o);
        fcs  += __shfl_xor_sync(0xffffffffu, fcs,  o);
        ces  += __shfl_xor_sync(0xffffffffu, ces,  o);
        cep  += __shfl_xor_sync(0xffffffffu, cep,  o);
        np   += __shfl_xor_sync(0xffffffffu, np,   o);
    }
    if (lane == 0) {
        sm[OFF_RL + warp] = locs; sm[OFF_RF + warp] = fcs;
        sm[OFF_RC + warp] = ces;  sm[OFF_RP + warp] = cep;
        ((int*)(sm + OFF_RN))[warp] = np;
    }
    __syncthreads();
    if (tid == 0) {
        float L=0.f,F=0.f,Ce=0.f,Cp=0.f; int Np=0;
        #pragma unroll
        for (int w = 0; w < 8; ++w) {
            L += sm[OFF_RL + w]; F += sm[OFF_RF + w];
            Ce += sm[OFF_RC + w]; Cp += sm[OFF_RP + w];
            Np += ((int*)(sm + OFF_RN))[w];
        }
        atomicAdd(&d_loss_l,  (double)L);
        atomicAdd(&d_loss_fc, (double)F);
        atomicAdd(&d_ce_all[b], (double)Ce);
        atomicAdd(&d_ce_pos[b], (double)Cp);
        atomicAdd(&d_numpos[b], Np);
    }

    // ---- completion handshake: last block does mining + finalize ----
    __threadfence();
    if (tid == 0) *s_isl = (atomicAdd(&d_done, 1) == NBLOCKS - 1);
    __syncthreads();
    if (!*s_isl) return;
    __threadfence();

    // overlay scratch for the fallback reductions onto the conf region
    int*    sh  = (int*)sm;                    // 256 ints  @ bytes [0,1024)
    double* shd = (double*)(sm + 256);         // 256 dbl   @ bytes [1024,3072)

    // per-row selection. fast path: num_neg >= #negatives -> row sum = all ce.
    if (tid == 0) *s_nfb = 0;
    __syncthreads();
    if (tid >= 64 && tid < 64 + BB) {          // avoid overlay region writers? (none yet)
        int r = tid - 64;
        int npb = d_numpos[r];
        long k3 = 3L * (long)npb;
        int k = (k3 < (long)(PP - 1)) ? (int)k3 : (PP - 1);
        int nneg = PP - npb;
        if (k >= nneg)      d_rowC[r] = d_ce_all[r];
        else if (k <= 0)    d_rowC[r] = d_ce_pos[r];
        else { int s = atomicAdd(s_nfb, 1); s_fbr[s] = r; }
    }
    __syncthreads();

    // exact fallback (never triggered on this data): recompute ce for the row,
    // then bit-bisection for the k-th largest negative ce.
    const int nfbv = *s_nfb;
    for (int fi = 0; fi < nfbv; ++fi) {
        int bb = s_fbr[fi];
        long rb = (long)bb * PP;
        for (int i = warp; i < PP; i += 8) {
            const long cb = (rb + i) * CC;
            float v0 = conf[cb + lane];
            float v1 = conf[cb + lane + 32];
            float v2 = (lane < CC - 64) ? conf[cb + lane + 64] : 0.f;
            float s = __expf(v0) + __expf(v1);
            if (lane < CC - 64) s += __expf(v2);
            #pragma unroll
            for (int o = 16; o; o >>= 1) s += __shfl_xor_sync(0xffffffffu, s, o);
            int t = conf_t[rb + i];
            float cand = (t < 32) ? v0 : (t < 64) ? v1 : v2;
            float gath = __shfl_sync(0xffffffffu, cand, t & 31);
            if (lane == 0) d_ce_row[i] = __logf(s) - gath;
        }
        __syncthreads();
        int npb = d_numpos[bb];
        long k3 = 3L * (long)npb;
        int k = (k3 < (long)(PP - 1)) ? (int)k3 : (PP - 1);
        unsigned lo = 0u, hi = 0x7f800000u;
        while (lo < hi) {
            unsigned mid = lo + (hi - lo + 1u) / 2u;
            int c = 0;
            for (int i = tid; i < PP; i += TPB)
                if (conf_t[rb + i] == 0 &&
                    __float_as_uint(fmaxf(d_ce_row[i], 0.f)) >= mid) c++;
            sh[tid] = c; __syncthreads();
            for (int s = TPB/2; s; s >>= 1) { if (tid < s) sh[tid] += sh[tid + s]; __syncthreads(); }
            int tot = sh[0]; __syncthreads();
            if (tot >= k) lo = mid; else hi = mid - 1u;
        }
        int c = 0; double su = 0.0;
        for (int i = tid; i < PP; i += TPB) {
            if (conf_t[rb + i] == 0) {
                float v = d_ce_row[i];
                if (__float_as_uint(fmaxf(v, 0.f)) > lo) { c++; su += (double)v; }
            }
        }
        sh[tid] = c; shd[tid] = su; __syncthreads();
        for (int s = TPB/2; s; s >>= 1) {
            if (tid < s) { sh[tid] += sh[tid + s]; shd[tid] += shd[tid + s]; }
            __syncthreads();
        }
        if (tid == 0)
            d_rowC[bb] = d_ce_pos[bb] + shd[0] + (double)(k - sh[0]) * (double)__uint_as_float(lo);
        __syncthreads();
    }

    // ---- finalize (parallel) ----
    double n = (tid < BB) ? (double)d_numpos[tid] : 0.0;
    double c = (tid < BB) ? d_rowC[tid] : 0.0;
    if (tid < 64) {
        #pragma unroll
        for (int o = 16; o; o >>= 1) {
            n += __shfl_xor_sync(0xffffffffu, n, o);
            c += __shfl_xor_sync(0xffffffffu, c, o);
        }
        if (lane == 0) { s_fin[(tid >> 5) * 2] = n; s_fin[(tid >> 5) * 2 + 1] = c; }
    }
    __syncthreads();
    if (tid == 0) {
        double N  = s_fin[0] + s_fin[2];
        double Cc = s_fin[1] + s_fin[3];
        out[0] = (float)(d_loss_l / N);
        out[1] = (float)(Cc / N);
        out[2] = (float)(d_loss_fc / N);
    }
}

extern "C" void kernel_launch(void* const* d_in, const int* in_sizes, int n_in,
                              void* d_out, int out_size) {
    const float* loc_data = (const float*)d_in[0];
    const float* conf     = (const float*)d_in[1];
    const float* fc_data  = (const float*)d_in[2];
    const float* loc_t    = (const float*)d_in[3];
    const float* fc_t     = (const float*)d_in[4];
    const int*   conf_t   = (const int*)d_in[5];

    cudaFuncSetAttribute(k_fused, cudaFuncAttributeMaxDynamicSharedMemorySize, SMEM_BYTES);
    k_init<<<1, 64>>>();
    dim3 grid(GRID_X, BB);
    k_fused<<<grid, TPB, SMEM_BYTES>>>(loc_data, conf, fc_data, loc_t, fc_t, conf_t, (float*)d_out);
}